// round 17
// baseline (speedup 1.0000x reference)
#include <cuda_runtime.h>

// ARModel p=1, C=1, out_dim=1:
//   out[b,t,n] = (t==0) ? 0 : x[b,t-1,n] * w + bias
// Flat over float4: out4[i] = x4[i - N4]*w + bias unless t(i)==0 (then 0).
//
// FINAL champion — complete sweep record:
//  - unroll/MLP {1,4,8}: 4 best (43.6 / 39.7 / 40.6 us)
//  - cache policy {.cs/.cs, .cs/.wb, L2::evict_last pin}: .cs/.cs best;
//    DRAM traffic constant ~240 MB under every policy -> no reuse exists
//  - scheduling {flat, persistent 1-wave}: flat best (persistent loop
//    serializes loads behind stores via register reuse)
//  - block size {256, 512}: 256 best (512 raises intra-SM L1tex queue
//    pressure: L1 43->67%, DRAM 76->70%)
//  - index math: hoisted — stride = 2,304,000 float4 = 4608 rows and
//    4608 % 288 == 0, so t/live are invariant across the unroll
// Result: ~39.7 us kernel = 7.43 TB/s effective = 93% of 8 TB/s spec.
// DRAM is the only busy pipe (fma 4%, alu 5%, issue 10%) — at the
// mixed read+write HBM3e streaming roofline.

#define AR_B 64
#define AR_T 288
#define AR_N 2000
#define AR_N4 (AR_N / 4)                       // 500
#define AR_TOTAL4 (AR_B * AR_T * AR_N4)        // 9,216,000
#define AR_UNROLL 4
#define AR_THREADS 256
#define AR_BLOCKS (AR_TOTAL4 / (AR_THREADS * AR_UNROLL))   // 9000 exact
#define AR_STRIDE (AR_BLOCKS * AR_THREADS)                 // 2,304,000 = 4608 rows

static_assert(AR_STRIDE % AR_N4 == 0, "stride not row-aligned");
static_assert((AR_STRIDE / AR_N4) % AR_T == 0, "t not invariant across unroll");

__global__ __launch_bounds__(AR_THREADS) void ar_model_kernel(
    const float4* __restrict__ x4,
    const float* __restrict__ w_ptr,
    const float* __restrict__ b_ptr,
    float4* __restrict__ out4)
{
    int base = blockIdx.x * AR_THREADS + threadIdx.x;

    // t invariant across the 4 strided elements: compute once per thread.
    int row  = base / AR_N4;          // (b*T + t) of element 0
    int t    = row % AR_T;
    bool live = (t != 0);

    const float W  = __ldg(w_ptr);
    const float Bi = __ldg(b_ptr);

    float4 v[AR_UNROLL];

    if (live) {
        // Front-batch 4 independent LDG.128 (streaming, evict-first).
        #pragma unroll
        for (int u = 0; u < AR_UNROLL; u++) {
            v[u] = __ldcs(&x4[base + u * AR_STRIDE - AR_N4]);
        }
        #pragma unroll
        for (int u = 0; u < AR_UNROLL; u++) {
            float4 o;
            o.x = fmaf(v[u].x, W, Bi);
            o.y = fmaf(v[u].y, W, Bi);
            o.z = fmaf(v[u].z, W, Bi);
            o.w = fmaf(v[u].w, W, Bi);
            __stcs(&out4[base + u * AR_STRIDE], o);
        }
    } else {
        float4 z;
        z.x = 0.0f; z.y = 0.0f; z.z = 0.0f; z.w = 0.0f;
        #pragma unroll
        for (int u = 0; u < AR_UNROLL; u++) {
            __stcs(&out4[base + u * AR_STRIDE], z);
        }
    }
}

extern "C" void kernel_launch(void* const* d_in, const int* in_sizes, int n_in,
                              void* d_out, int out_size)
{
    const float4* x4 = (const float4*)d_in[0];
    const float*  w  = (const float*)d_in[1];
    const float*  b  = (const float*)d_in[2];
    float4* out4 = (float4*)d_out;

    ar_model_kernel<<<AR_BLOCKS, AR_THREADS>>>(x4, w, b, out4);
}